// round 14
// baseline (speedup 1.0000x reference)
#include <cuda_runtime.h>
#include <cuda_fp16.h>
#include <math.h>
#include <stdint.h>

#define D_MODEL 1024
#define NH      16
#define DH      64
#define BATCH   2
#define SEQ     2048
#define NTOK    (BATCH * SEQ)   // 4096

// Scratch (device globals — no runtime allocation allowed)
__device__ __half g_xh [NTOK * D_MODEL];       // x in fp16
__device__ __half g_wqh[D_MODEL * D_MODEL];
__device__ __half g_wkh[D_MODEL * D_MODEL];
__device__ __half g_wvh[D_MODEL * D_MODEL];
__device__ __half g_woh[D_MODEL * D_MODEL];
__device__ __half g_q16 [NTOK * D_MODEL];      // Q fp16, pre-scaled by 0.125*log2(e)
__device__ __half g_k16 [NTOK * D_MODEL];      // K fp16 [token][chan]
__device__ __half g_vt16[D_MODEL * NTOK];      // V^T fp16 [chan][token]
__device__ __half g_ctx [NTOK * D_MODEL];      // attention output fp16

__device__ __forceinline__ uint32_t smem_u32(const void* p) {
    uint32_t a;
    asm("{ .reg .u64 t; cvta.to.shared.u64 t, %1; cvt.u32.u64 %0, t; }" : "=r"(a) : "l"(p));
    return a;
}
__device__ __forceinline__ void ldsm_x4(uint32_t (&r)[4], uint32_t addr) {
    asm volatile("ldmatrix.sync.aligned.m8n8.x4.shared.b16 {%0,%1,%2,%3}, [%4];"
                 : "=r"(r[0]), "=r"(r[1]), "=r"(r[2]), "=r"(r[3]) : "r"(addr));
}
// fp16 mma with fp32 accumulate
__device__ __forceinline__ void mma_f16(float (&c)[4], const uint32_t a[4],
                                        uint32_t b0, uint32_t b1) {
    asm volatile(
        "mma.sync.aligned.m16n8k16.row.col.f32.f16.f16.f32 "
        "{%0,%1,%2,%3}, {%4,%5,%6,%7}, {%8,%9}, {%0,%1,%2,%3};"
        : "+f"(c[0]), "+f"(c[1]), "+f"(c[2]), "+f"(c[3])
        : "r"(a[0]), "r"(a[1]), "r"(a[2]), "r"(a[3]), "r"(b0), "r"(b1));
}
__device__ __forceinline__ float ex2(float x) {
    float y; asm("ex2.approx.f32 %0, %1;" : "=f"(y) : "f"(x)); return y;
}
#define CP_ASYNC16(dst, src) \
    asm volatile("cp.async.cg.shared.global [%0], [%1], 16;" :: "r"(dst), "l"(src) : "memory")
#define CP_COMMIT() asm volatile("cp.async.commit_group;" ::: "memory")
#define CP_WAIT0()  asm volatile("cp.async.wait_group 0;" ::: "memory")
#define CP_WAIT1()  asm volatile("cp.async.wait_group 1;" ::: "memory")

// ============================================================================
// fp32 -> fp16 conversion. Single-tensor variant (x) and 4-way variant (Ws).
// ============================================================================
__global__ __launch_bounds__(256) void f2h(const float* __restrict__ in,
                                           __half* __restrict__ out, int n)
{
    int i = (blockIdx.x * 256 + threadIdx.x) * 4;
    if (i < n) {
        float4 v = *reinterpret_cast<const float4*>(in + i);
        __half2 h0 = __floats2half2_rn(v.x, v.y);
        __half2 h1 = __floats2half2_rn(v.z, v.w);
        uint2 pk = make_uint2(*reinterpret_cast<uint32_t*>(&h0),
                              *reinterpret_cast<uint32_t*>(&h1));
        *reinterpret_cast<uint2*>(out + i) = pk;
    }
}
__global__ __launch_bounds__(256) void f2h4(
    const float* __restrict__ i0, const float* __restrict__ i1,
    const float* __restrict__ i2, const float* __restrict__ i3,
    __half* __restrict__ o0, __half* __restrict__ o1,
    __half* __restrict__ o2, __half* __restrict__ o3, int n)
{
    const float* in  = (blockIdx.y == 0) ? i0 : (blockIdx.y == 1) ? i1
                     : (blockIdx.y == 2) ? i2 : i3;
    __half* out      = (blockIdx.y == 0) ? o0 : (blockIdx.y == 1) ? o1
                     : (blockIdx.y == 2) ? o2 : o3;
    int i = (blockIdx.x * 256 + threadIdx.x) * 4;
    if (i < n) {
        float4 v = *reinterpret_cast<const float4*>(in + i);
        __half2 h0 = __floats2half2_rn(v.x, v.y);
        __half2 h1 = __floats2half2_rn(v.z, v.w);
        uint2 pk = make_uint2(*reinterpret_cast<uint32_t*>(&h0),
                              *reinterpret_cast<uint32_t*>(&h1));
        *reinterpret_cast<uint2*>(out + i) = pk;
    }
}

// ============================================================================
// Shared fp16 GEMM body (unchanged, measured-best): 2-stage cp.async.
// ============================================================================
#define BM 128
#define BN 128
#define BKH 64
#define KSTRH 72
#define TILE_H (BM * KSTRH)
#define GSMEM_BYTES (4 * TILE_H * 2)
#define GK 1024

#define QSCALEF (0.125f * 1.4426950408889634f)

template <bool FP32OUT>
__device__ __forceinline__ void hgemm_body(
    __half* smh, const __half* __restrict__ A, const __half* __restrict__ W,
    void* __restrict__ Cv, int N, int bm, int bn, float scale)
{
    __half* AsP[2] = { smh,              smh + TILE_H };
    __half* BsP[2] = { smh + 2 * TILE_H, smh + 3 * TILE_H };

    const int tid  = threadIdx.x;
    const int wid  = tid >> 5;
    const int lane = tid & 31;
    const int wm = (wid >> 2) * 64;
    const int wn = (wid & 3) * 32;

    float acc[4][4][4];
#pragma unroll
    for (int i = 0; i < 4; i++)
#pragma unroll
        for (int j = 0; j < 4; j++)
#pragma unroll
            for (int q = 0; q < 4; q++) acc[i][j][q] = 0.f;

    const int aj   = lane >> 3;
    const int mrow = ((aj & 1) << 3) + (lane & 7);
    const int mcol = (aj >> 1) << 4;

    uint32_t aBase[2], bBase[2];
#pragma unroll
    for (int buf = 0; buf < 2; buf++) {
        aBase[buf] = smem_u32(AsP[buf]) + (uint32_t)(wm + mrow) * (KSTRH * 2) + mcol;
        bBase[buf] = smem_u32(BsP[buf]) + (uint32_t)(wn + mrow) * (KSTRH * 2) + mcol;
    }

    const __half* Ap = A + (size_t)bm * GK;
    const __half* Wp = W + (size_t)bn * GK;
    const int KT = GK / BKH;

    auto load_tile = [&](int t, int buf) {
        const __half* Ag = Ap + t * BKH;
        const __half* Bg = Wp + t * BKH;
        uint32_t sa = smem_u32(AsP[buf]);
        uint32_t sb = smem_u32(BsP[buf]);
#pragma unroll
        for (int i = 0; i < 4; i++) {
            int chunk = tid + 256 * i;
            int row = chunk >> 3;
            int c   = chunk & 7;
            uint32_t so = (uint32_t)row * (KSTRH * 2) + c * 16;
            CP_ASYNC16(sa + so, __cvta_generic_to_global(Ag + (size_t)row * GK + c * 8));
            CP_ASYNC16(sb + so, __cvta_generic_to_global(Bg + (size_t)row * GK + c * 8));
        }
        CP_COMMIT();
    };

    load_tile(0, 0);

    for (int t = 0; t < KT; t++) {
        const int buf = t & 1;
        if (t + 1 < KT) { load_tile(t + 1, buf ^ 1); CP_WAIT1(); }
        else           { CP_WAIT0(); }
        __syncthreads();

#pragma unroll
        for (int ks = 0; ks < 4; ks++) {
            uint32_t afr[4][4], bfr[2][4];
#pragma unroll
            for (int mt = 0; mt < 4; mt++)
                ldsm_x4(afr[mt], aBase[buf] + (uint32_t)(mt * 16 * KSTRH * 2) + ks * 32);
#pragma unroll
            for (int p = 0; p < 2; p++)
                ldsm_x4(bfr[p], bBase[buf] + (uint32_t)(p * 16 * KSTRH * 2) + ks * 32);
#pragma unroll
            for (int mt = 0; mt < 4; mt++) {
#pragma unroll
                for (int p = 0; p < 2; p++) {
                    mma_f16(acc[mt][2 * p],     afr[mt], bfr[p][0], bfr[p][2]);
                    mma_f16(acc[mt][2 * p + 1], afr[mt], bfr[p][1], bfr[p][3]);
                }
            }
        }
        __syncthreads();
    }

    const int rr = lane >> 2;
    const int cc = (lane & 3) * 2;
#pragma unroll
    for (int mt = 0; mt < 4; mt++) {
#pragma unroll
        for (int nt = 0; nt < 4; nt++) {
            int row = bm + wm + mt * 16 + rr;
            int col = bn + wn + nt * 8 + cc;
            if (FP32OUT) {
                float* Cp = (float*)Cv;
                *reinterpret_cast<float2*>(Cp + (size_t)row * N + col)
                    = make_float2(acc[mt][nt][0], acc[mt][nt][1]);
                *reinterpret_cast<float2*>(Cp + (size_t)(row + 8) * N + col)
                    = make_float2(acc[mt][nt][2], acc[mt][nt][3]);
            } else {
                __half* Cp = (__half*)Cv;
                __half2 v0 = __floats2half2_rn(acc[mt][nt][0] * scale, acc[mt][nt][1] * scale);
                __half2 v1 = __floats2half2_rn(acc[mt][nt][2] * scale, acc[mt][nt][3] * scale);
                *reinterpret_cast<__half2*>(Cp + (size_t)row * N + col)       = v0;
                *reinterpret_cast<__half2*>(Cp + (size_t)(row + 8) * N + col) = v1;
            }
        }
    }
}

// Merged Q/K/V^T GEMM: 768 CTAs in ONE launch
__global__ __launch_bounds__(256, 2) void qkv_gemm(
    const __half* __restrict__ xh,
    const __half* __restrict__ wqh, const __half* __restrict__ wkh,
    const __half* __restrict__ wvh,
    __half* __restrict__ q16, __half* __restrict__ k16, __half* __restrict__ vt16)
{
    extern __shared__ __half smh[];
    const int id = blockIdx.x;
    const __half *A, *W;
    __half* C;
    int N, bm, bn;
    float scale;
    if (id < 512) {
        A = xh;
        W = (id < 256) ? wqh : wkh;
        C = (id < 256) ? q16 : k16;
        scale = (id < 256) ? QSCALEF : 1.0f;
        int t = id & 255;
        bn = (t & 7) * BN;
        bm = (t >> 3) * BM;
        N = D_MODEL;
    } else {
        A = wvh; W = xh; C = vt16; scale = 1.0f;
        int t = id - 512;
        bn = (t & 31) * BN;
        bm = (t >> 5) * BM;
        N = NTOK;
    }
    hgemm_body<false>(smh, A, W, (void*)C, N, bm, bn, scale);
}

__global__ __launch_bounds__(256, 2) void out_gemm(
    const __half* __restrict__ ctx, const __half* __restrict__ woh,
    float* __restrict__ out)
{
    extern __shared__ __half smh[];
    int bn = (blockIdx.x & 7) * BN;
    int bm = (blockIdx.x >> 3) * BM;
    hgemm_body<true>(smh, ctx, woh, (void*)out, D_MODEL, bm, bn, 1.0f);
}

// ============================================================================
// fp16 causal flash attention — R14: cross-tile software pipeline.
// Iteration kt: S(kt) mma burst -> PV(kt-1) mma burst -> softmax(kt)+STS P(kt).
// PV lags one tile so its tensor work hides S-wait + softmax latency.
// P in warp-private smem (reuses Q region). V triple-buffered.
// smem: Q/P [128][72] | K x2 [64][72] | V^T x3 [64][72] = 63 KB -> 2 CTA/SM
// ============================================================================
#define ASTRH 72
#define AQ_OFF    0
#define AK_OFF(b) (128 * ASTRH + (b) * 64 * ASTRH)
#define AV_OFF(b) (128 * ASTRH + 2 * 64 * ASTRH + (b) * 64 * ASTRH)
#define AT_H      (128 * ASTRH + 5 * 64 * ASTRH)
#define AT_BYTES  (AT_H * 2)                 // 64512

__global__ __launch_bounds__(256, 2) void attn_mma(
    const __half* __restrict__ Q, const __half* __restrict__ Kp,
    const __half* __restrict__ Vt, __half* __restrict__ O)
{
    extern __shared__ __half smh[];
    const int tid  = threadIdx.x;
    const int wid  = tid >> 5;
    const int lane = tid & 31;
    const int qt   = (SEQ / 128 - 1) - blockIdx.x;   // long blocks first
    const int h    = blockIdx.y;
    const int b    = blockIdx.z;
    const int q0   = qt * 128;
    const int nkt  = 2 * qt + 2;
    const size_t hb = (size_t)b * SEQ * D_MODEL + (size_t)h * DH;

    auto load_k = [&](int kt, int buf) {
        uint32_t dst = smem_u32(smh + AK_OFF(buf));
        const __half* Kg = Kp + hb + (size_t)kt * 64 * D_MODEL;
#pragma unroll
        for (int i = 0; i < 2; i++) {
            int chunk = tid + 256 * i;
            int row = chunk >> 3, c = chunk & 7;
            CP_ASYNC16(dst + (uint32_t)row * (ASTRH * 2) + c * 16,
                       __cvta_generic_to_global(Kg + (size_t)row * D_MODEL + c * 8));
        }
    };
    auto load_v = [&](int kt, int buf) {
        uint32_t dst = smem_u32(smh + AV_OFF(buf));
        const __half* Vg = Vt + (size_t)h * 64 * NTOK + (size_t)b * SEQ + (size_t)kt * 64;
#pragma unroll
        for (int i = 0; i < 2; i++) {
            int chunk = tid + 256 * i;
            int d = chunk >> 3, c = chunk & 7;
            CP_ASYNC16(dst + (uint32_t)d * (ASTRH * 2) + c * 16,
                       __cvta_generic_to_global(Vg + (size_t)d * NTOK + c * 8));
        }
    };

    // prologue: Q (group0), K0+V0 (group1)
    {
        uint32_t qdst = smem_u32(smh + AQ_OFF);
#pragma unroll
        for (int i = 0; i < 4; i++) {
            int chunk = tid + 256 * i;
            int row = chunk >> 3, c = chunk & 7;
            CP_ASYNC16(qdst + (uint32_t)row * (ASTRH * 2) + c * 16,
                       __cvta_generic_to_global(Q + hb + (size_t)(q0 + row) * D_MODEL + c * 8));
        }
        CP_COMMIT();
    }
    load_k(0, 0);
    load_v(0, 0);
    CP_COMMIT();

    const int aj   = lane >> 3;
    const int mrow = ((aj & 1) << 3) + (lane & 7);
    const int mcol = (aj >> 1) << 4;
    const int wq   = wid * 16;

    CP_WAIT1();
    __syncthreads();

    // Preload Q fragments (pre-scaled in GEMM epilogue)
    uint32_t qfr[4][4];
    {
        uint32_t qa = smem_u32(smh + AQ_OFF) + (uint32_t)(wq + mrow) * (ASTRH * 2) + mcol;
#pragma unroll
        for (int ks = 0; ks < 4; ks++) ldsm_x4(qfr[ks], qa + ks * 32);
    }
    // Q smem reused as warp-private P (all threads hold Q frags before 1st STS)

    __half* Ps = smh + AQ_OFF;
    const uint32_t pLd = smem_u32(Ps) + (uint32_t)(wq + mrow) * (ASTRH * 2) + mcol;
    const uint32_t kB[2] = { smem_u32(smh + AK_OFF(0)) + (uint32_t)mrow * (ASTRH * 2) + mcol,
                             smem_u32(smh + AK_OFF(1)) + (uint32_t)mrow * (ASTRH * 2) + mcol };
    const uint32_t vB[3] = { smem_u32(smh + AV_OFF(0)) + (uint32_t)mrow * (ASTRH * 2) + mcol,
                             smem_u32(smh + AV_OFF(1)) + (uint32_t)mrow * (ASTRH * 2) + mcol,
                             smem_u32(smh + AV_OFF(2)) + (uint32_t)mrow * (ASTRH * 2) + mcol };

    float oacc[8][4];
#pragma unroll
    for (int nt = 0; nt < 8; nt++)
#pragma unroll
        for (int r = 0; r < 4; r++) oacc[nt][r] = 0.f;
    float m0 = -INFINITY, m1 = -INFINITY, l0 = 0.f, l1 = 0.f;

    const int lr = lane >> 2;
    const int lc = (lane & 3) * 2;

    // ---- S = Q K^T into sacc ----
    auto s_mma = [&](int kbuf, float (&sacc)[8][4]) {
#pragma unroll
        for (int nt = 0; nt < 8; nt++)
#pragma unroll
            for (int r = 0; r < 4; r++) sacc[nt][r] = 0.f;
#pragma unroll
        for (int ks = 0; ks < 4; ks++) {
#pragma unroll
            for (int p = 0; p < 4; p++) {
                uint32_t kf[4];
                ldsm_x4(kf, kB[kbuf] + (uint32_t)(p * 16 * ASTRH * 2) + ks * 32);
                mma_f16(sacc[2 * p],     qfr[ks], kf[0], kf[2]);
                mma_f16(sacc[2 * p + 1], qfr[ks], kf[1], kf[3]);
            }
        }
    };

    // ---- O += P V (P from warp-private smem, V from vbuf) ----
    auto pv_mma = [&](int vbuf) {
#pragma unroll
        for (int ks = 0; ks < 4; ks++) {
            uint32_t pf[4];
            ldsm_x4(pf, pLd + ks * 32);
#pragma unroll
            for (int p = 0; p < 4; p++) {
                uint32_t vf[4];
                ldsm_x4(vf, vB[vbuf] + (uint32_t)(p * 16 * ASTRH * 2) + ks * 32);
                mma_f16(oacc[2 * p],     pf, vf[0], vf[2]);
                mma_f16(oacc[2 * p + 1], pf, vf[1], vf[3]);
            }
        }
    };

    // ---- mask + online softmax + store P ----
    auto softmax_sts = [&](int k0, bool diag, float (&sacc)[8][4]) {
        const int rg0 = q0 + wq + lr;
        if (diag) {
#pragma unroll
            for (int nt = 0; nt < 8; nt++) {
                int cb = k0 + nt * 8 + lc;
                if (cb     > rg0)     sacc[nt][0] = -1e30f;
                if (cb + 1 > rg0)     sacc[nt][1] = -1e30f;
                if (cb     > rg0 + 8) sacc[nt][2] = -1e30f;
                if (cb + 1 > rg0 + 8) sacc[nt][3] = -1e30f;
            }
        }
        float mx0 = -1e30f, mx1 = -1e30f;
#pragma unroll
        for (int nt = 0; nt < 8; nt++) {
            mx0 = fmaxf(mx0, fmaxf(sacc[nt][0], sacc[nt][1]));
            mx1 = fmaxf(mx1, fmaxf(sacc[nt][2], sacc[nt][3]));
        }
        mx0 = fmaxf(mx0, __shfl_xor_sync(0xffffffffu, mx0, 1));
        mx0 = fmaxf(mx0, __shfl_xor_sync(0xffffffffu, mx0, 2));
        mx1 = fmaxf(mx1, __shfl_xor_sync(0xffffffffu, mx1, 1));
        mx1 = fmaxf(mx1, __shfl_xor_sync(0xffffffffu, mx1, 2));
        float mn0 = fmaxf(m0, mx0), mn1 = fmaxf(m1, mx1);
        float a0 = ex2(m0 - mn0), a1 = ex2(m1 - mn1);
        float rs0 = 0.f, rs1 = 0.f;
#pragma unroll
        for (int nt = 0; nt < 8; nt++) {
            float e0 = ex2(sacc[nt][0] - mn0);
            float e1 = ex2(sacc[nt][1] - mn0);
            float e2 = ex2(sacc[nt][2] - mn1);
            float e3 = ex2(sacc[nt][3] - mn1);
            sacc[nt][0] = e0; sacc[nt][1] = e1; sacc[nt][2] = e2; sacc[nt][3] = e3;
            rs0 += e0 + e1; rs1 += e2 + e3;
        }
        rs0 += __shfl_xor_sync(0xffffffffu, rs0, 1);
        rs0 += __shfl_xor_sync(0xffffffffu, rs0, 2);
        rs1 += __shfl_xor_sync(0xffffffffu, rs1, 1);
        rs1 += __shfl_xor_sync(0xffffffffu, rs1, 2);
        l0 = l0 * a0 + rs0; m0 = mn0;
        l1 = l1 * a1 + rs1; m1 = mn1;
#pragma unroll
        for (int nt = 0; nt < 8; nt++) {
            oacc[nt][0] *= a0; oacc[nt][1] *= a0;
            oacc[nt][2] *= a1; oacc[nt][3] *= a1;
        }
        __half* pr0 = Ps + (wq + lr) * ASTRH + lc;
        __half* pr1 = pr0 + 8 * ASTRH;
#pragma unroll
        for (int nt = 0; nt < 8; nt++) {
            *reinterpret_cast<__half2*>(pr0 + nt * 8)
                = __floats2half2_rn(sacc[nt][0], sacc[nt][1]);
            *reinterpret_cast<__half2*>(pr1 + nt * 8)
                = __floats2half2_rn(sacc[nt][2], sacc[nt][3]);
        }
        __syncwarp();
    };

    // ---- peeled iteration 0 ----
    {
        CP_WAIT0();
        __syncthreads();
        load_k(1, 1);              // nkt >= 2 always
        load_v(1, 1);
        CP_COMMIT();
        float sacc[8][4];
        s_mma(0, sacc);
        softmax_sts(0, qt == 0, sacc);
    }

    // ---- main pipelined loop ----
    for (int kt = 1; kt < nkt; kt++) {
        CP_WAIT0();                // K(kt), V(kt) resident
        __syncthreads();           // all warps done with K[(kt)&1^1]/V[(kt+2)%3] reads
        if (kt + 1 < nkt) {
            load_k(kt + 1, (kt + 1) & 1);
            load_v(kt + 1, (kt + 1) % 3);
            CP_COMMIT();
        }
        float sacc[8][4];
        s_mma(kt & 1, sacc);       // S(kt): independent of P(kt-1)
        pv_mma((kt - 1) % 3);      // PV(kt-1): tensor work overlapping softmax below
        softmax_sts(kt * 64, kt >= 2 * qt, sacc);
    }
    // ---- final PV ----
    pv_mma((nkt - 1) % 3);

    // ---- epilogue: fp16 ctx ----
    const float i0 = 1.f / l0, i1 = 1.f / l1;
    const int row0 = q0 + wq + lr;
    __half* Ob = O + (size_t)(b * SEQ + row0) * D_MODEL + (size_t)h * DH + lc;
#pragma unroll
    for (int nt = 0; nt < 8; nt++) {
        *reinterpret_cast<__half2*>(Ob + nt * 8)
            = __floats2half2_rn(oacc[nt][0] * i0, oacc[nt][1] * i0);
        *reinterpret_cast<__half2*>(Ob + 8 * D_MODEL + nt * 8)
            = __floats2half2_rn(oacc[nt][2] * i1, oacc[nt][3] * i1);
    }
}

// ---------------------------------------------------------------------------
extern "C" void kernel_launch(void* const* d_in, const int* in_sizes, int n_in,
                              void* d_out, int out_size)
{
    const float* x  = (const float*)d_in[0];
    const float* Wq = (const float*)d_in[1];
    const float* Wk = (const float*)d_in[2];
    const float* Wv = (const float*)d_in[3];
    const float* Wo = (const float*)d_in[4];
    float* out = (float*)d_out;

    __half *xh, *wqh, *wkh, *wvh, *woh, *q16, *k16, *vt16, *ctx;
    cudaGetSymbolAddress((void**)&xh,   g_xh);
    cudaGetSymbolAddress((void**)&wqh,  g_wqh);
    cudaGetSymbolAddress((void**)&wkh,  g_wkh);
    cudaGetSymbolAddress((void**)&wvh,  g_wvh);
    cudaGetSymbolAddress((void**)&woh,  g_woh);
    cudaGetSymbolAddress((void**)&q16,  g_q16);
    cudaGetSymbolAddress((void**)&k16,  g_k16);
    cudaGetSymbolAddress((void**)&vt16, g_vt16);
    cudaGetSymbolAddress((void**)&ctx,  g_ctx);

    cudaFuncSetAttribute(qkv_gemm, cudaFuncAttributeMaxDynamicSharedMemorySize, GSMEM_BYTES);
    cudaFuncSetAttribute(out_gemm, cudaFuncAttributeMaxDynamicSharedMemorySize, GSMEM_BYTES);
    cudaFuncSetAttribute(attn_mma, cudaFuncAttributeMaxDynamicSharedMemorySize, AT_BYTES);

    const int NX = NTOK * D_MODEL, NW = D_MODEL * D_MODEL;
    f2h<<<NX / 1024, 256>>>(x, xh, NX);
    f2h4<<<dim3(NW / 1024, 4), 256>>>(Wq, Wk, Wv, Wo, wqh, wkh, wvh, woh, NW);

    qkv_gemm<<<768, 256, GSMEM_BYTES>>>(xh, wqh, wkh, wvh, q16, k16, vt16);

    attn_mma<<<dim3(SEQ / 128, NH, BATCH), 256, AT_BYTES>>>(q16, k16, vt16, ctx);

    out_gemm<<<256, 256, GSMEM_BYTES>>>(ctx, woh, out);
}

// round 15
// speedup vs baseline: 1.1839x; 1.1839x over previous
#include <cuda_runtime.h>
#include <cuda_fp16.h>
#include <math.h>
#include <stdint.h>

#define D_MODEL 1024
#define NH      16
#define DH      64
#define BATCH   2
#define SEQ     2048
#define NTOK    (BATCH * SEQ)   // 4096

// Scratch (device globals — no runtime allocation allowed)
__device__ __half g_xh [NTOK * D_MODEL];       // x in fp16
__device__ __half g_wqh[D_MODEL * D_MODEL];
__device__ __half g_wkh[D_MODEL * D_MODEL];
__device__ __half g_wvh[D_MODEL * D_MODEL];
__device__ __half g_woh[D_MODEL * D_MODEL];
__device__ __half g_q16 [NTOK * D_MODEL];      // Q fp16, pre-scaled by 0.125*log2(e)
__device__ __half g_k16 [NTOK * D_MODEL];      // K fp16 [token][chan]
__device__ __half g_vt16[D_MODEL * NTOK];      // V^T fp16 [chan][token]
__device__ __half g_ctx [NTOK * D_MODEL];      // attention output fp16

__device__ __forceinline__ uint32_t smem_u32(const void* p) {
    uint32_t a;
    asm("{ .reg .u64 t; cvta.to.shared.u64 t, %1; cvt.u32.u64 %0, t; }" : "=r"(a) : "l"(p));
    return a;
}
__device__ __forceinline__ void ldsm_x4(uint32_t (&r)[4], uint32_t addr) {
    asm volatile("ldmatrix.sync.aligned.m8n8.x4.shared.b16 {%0,%1,%2,%3}, [%4];"
                 : "=r"(r[0]), "=r"(r[1]), "=r"(r[2]), "=r"(r[3]) : "r"(addr));
}
// fp16 mma with fp32 accumulate
__device__ __forceinline__ void mma_f16(float (&c)[4], const uint32_t a[4],
                                        uint32_t b0, uint32_t b1) {
    asm volatile(
        "mma.sync.aligned.m16n8k16.row.col.f32.f16.f16.f32 "
        "{%0,%1,%2,%3}, {%4,%5,%6,%7}, {%8,%9}, {%0,%1,%2,%3};"
        : "+f"(c[0]), "+f"(c[1]), "+f"(c[2]), "+f"(c[3])
        : "r"(a[0]), "r"(a[1]), "r"(a[2]), "r"(a[3]), "r"(b0), "r"(b1));
}
__device__ __forceinline__ float ex2(float x) {
    float y; asm("ex2.approx.f32 %0, %1;" : "=f"(y) : "f"(x)); return y;
}
__device__ __forceinline__ uint32_t pack_h2(float a, float b) {
    __half2 h = __floats2half2_rn(a, b);
    return *reinterpret_cast<uint32_t*>(&h);
}
#define CP_ASYNC16(dst, src) \
    asm volatile("cp.async.cg.shared.global [%0], [%1], 16;" :: "r"(dst), "l"(src) : "memory")
#define CP_COMMIT() asm volatile("cp.async.commit_group;" ::: "memory")
#define CP_WAIT0()  asm volatile("cp.async.wait_group 0;" ::: "memory")
#define CP_WAIT1()  asm volatile("cp.async.wait_group 1;" ::: "memory")

// ============================================================================
// Merged fp32 -> fp16 conversion: ONE launch converts x + all 4 weights.
// 8192 blocks x 256 threads x 4 elems. Blocks 0..4095: x; then 1024 per W.
// ============================================================================
__global__ __launch_bounds__(256) void f2h_all(
    const float* __restrict__ x,
    const float* __restrict__ wq, const float* __restrict__ wk,
    const float* __restrict__ wv, const float* __restrict__ wo,
    __half* __restrict__ xh,
    __half* __restrict__ wqh, __half* __restrict__ wkh,
    __half* __restrict__ wvh, __half* __restrict__ woh)
{
    const int id = blockIdx.x;
    const float* in;
    __half* out;
    int boff;
    if (id < 4096) { in = x; out = xh; boff = id; }
    else {
        int w = (id - 4096) >> 10;        // 0..3
        boff  = (id - 4096) & 1023;
        in  = (w == 0) ? wq : (w == 1) ? wk : (w == 2) ? wv : wo;
        out = (w == 0) ? wqh : (w == 1) ? wkh : (w == 2) ? wvh : woh;
    }
    int i = (boff * 256 + threadIdx.x) * 4;
    float4 v = *reinterpret_cast<const float4*>(in + i);
    __half2 h0 = __floats2half2_rn(v.x, v.y);
    __half2 h1 = __floats2half2_rn(v.z, v.w);
    uint2 pk = make_uint2(*reinterpret_cast<uint32_t*>(&h0),
                          *reinterpret_cast<uint32_t*>(&h1));
    *reinterpret_cast<uint2*>(out + i) = pk;
}

// ============================================================================
// Shared fp16 GEMM body (measured-best): 2-stage cp.async double buffer.
// ============================================================================
#define BM 128
#define BN 128
#define BKH 64
#define KSTRH 72
#define TILE_H (BM * KSTRH)
#define GSMEM_BYTES (4 * TILE_H * 2)
#define GK 1024

#define QSCALEF (0.125f * 1.4426950408889634f)

template <bool FP32OUT>
__device__ __forceinline__ void hgemm_body(
    __half* smh, const __half* __restrict__ A, const __half* __restrict__ W,
    void* __restrict__ Cv, int N, int bm, int bn, float scale)
{
    __half* AsP[2] = { smh,              smh + TILE_H };
    __half* BsP[2] = { smh + 2 * TILE_H, smh + 3 * TILE_H };

    const int tid  = threadIdx.x;
    const int wid  = tid >> 5;
    const int lane = tid & 31;
    const int wm = (wid >> 2) * 64;
    const int wn = (wid & 3) * 32;

    float acc[4][4][4];
#pragma unroll
    for (int i = 0; i < 4; i++)
#pragma unroll
        for (int j = 0; j < 4; j++)
#pragma unroll
            for (int q = 0; q < 4; q++) acc[i][j][q] = 0.f;

    const int aj   = lane >> 3;
    const int mrow = ((aj & 1) << 3) + (lane & 7);
    const int mcol = (aj >> 1) << 4;

    uint32_t aBase[2], bBase[2];
#pragma unroll
    for (int buf = 0; buf < 2; buf++) {
        aBase[buf] = smem_u32(AsP[buf]) + (uint32_t)(wm + mrow) * (KSTRH * 2) + mcol;
        bBase[buf] = smem_u32(BsP[buf]) + (uint32_t)(wn + mrow) * (KSTRH * 2) + mcol;
    }

    const __half* Ap = A + (size_t)bm * GK;
    const __half* Wp = W + (size_t)bn * GK;
    const int KT = GK / BKH;

    auto load_tile = [&](int t, int buf) {
        const __half* Ag = Ap + t * BKH;
        const __half* Bg = Wp + t * BKH;
        uint32_t sa = smem_u32(AsP[buf]);
        uint32_t sb = smem_u32(BsP[buf]);
#pragma unroll
        for (int i = 0; i < 4; i++) {
            int chunk = tid + 256 * i;
            int row = chunk >> 3;
            int c   = chunk & 7;
            uint32_t so = (uint32_t)row * (KSTRH * 2) + c * 16;
            CP_ASYNC16(sa + so, __cvta_generic_to_global(Ag + (size_t)row * GK + c * 8));
            CP_ASYNC16(sb + so, __cvta_generic_to_global(Bg + (size_t)row * GK + c * 8));
        }
        CP_COMMIT();
    };

    load_tile(0, 0);

    for (int t = 0; t < KT; t++) {
        const int buf = t & 1;
        if (t + 1 < KT) { load_tile(t + 1, buf ^ 1); CP_WAIT1(); }
        else           { CP_WAIT0(); }
        __syncthreads();

#pragma unroll
        for (int ks = 0; ks < 4; ks++) {
            uint32_t afr[4][4], bfr[2][4];
#pragma unroll
            for (int mt = 0; mt < 4; mt++)
                ldsm_x4(afr[mt], aBase[buf] + (uint32_t)(mt * 16 * KSTRH * 2) + ks * 32);
#pragma unroll
            for (int p = 0; p < 2; p++)
                ldsm_x4(bfr[p], bBase[buf] + (uint32_t)(p * 16 * KSTRH * 2) + ks * 32);
#pragma unroll
            for (int mt = 0; mt < 4; mt++) {
#pragma unroll
                for (int p = 0; p < 2; p++) {
                    mma_f16(acc[mt][2 * p],     afr[mt], bfr[p][0], bfr[p][2]);
                    mma_f16(acc[mt][2 * p + 1], afr[mt], bfr[p][1], bfr[p][3]);
                }
            }
        }
        __syncthreads();
    }

    const int rr = lane >> 2;
    const int cc = (lane & 3) * 2;
#pragma unroll
    for (int mt = 0; mt < 4; mt++) {
#pragma unroll
        for (int nt = 0; nt < 4; nt++) {
            int row = bm + wm + mt * 16 + rr;
            int col = bn + wn + nt * 8 + cc;
            if (FP32OUT) {
                float* Cp = (float*)Cv;
                *reinterpret_cast<float2*>(Cp + (size_t)row * N + col)
                    = make_float2(acc[mt][nt][0], acc[mt][nt][1]);
                *reinterpret_cast<float2*>(Cp + (size_t)(row + 8) * N + col)
                    = make_float2(acc[mt][nt][2], acc[mt][nt][3]);
            } else {
                __half* Cp = (__half*)Cv;
                __half2 v0 = __floats2half2_rn(acc[mt][nt][0] * scale, acc[mt][nt][1] * scale);
                __half2 v1 = __floats2half2_rn(acc[mt][nt][2] * scale, acc[mt][nt][3] * scale);
                *reinterpret_cast<__half2*>(Cp + (size_t)row * N + col)       = v0;
                *reinterpret_cast<__half2*>(Cp + (size_t)(row + 8) * N + col) = v1;
            }
        }
    }
}

// Merged Q/K/V^T GEMM: 768 CTAs in ONE launch
__global__ __launch_bounds__(256, 2) void qkv_gemm(
    const __half* __restrict__ xh,
    const __half* __restrict__ wqh, const __half* __restrict__ wkh,
    const __half* __restrict__ wvh,
    __half* __restrict__ q16, __half* __restrict__ k16, __half* __restrict__ vt16)
{
    extern __shared__ __half smh[];
    const int id = blockIdx.x;
    const __half *A, *W;
    __half* C;
    int N, bm, bn;
    float scale;
    if (id < 512) {
        A = xh;
        W = (id < 256) ? wqh : wkh;
        C = (id < 256) ? q16 : k16;
        scale = (id < 256) ? QSCALEF : 1.0f;
        int t = id & 255;
        bn = (t & 7) * BN;
        bm = (t >> 3) * BM;
        N = D_MODEL;
    } else {
        A = wvh; W = xh; C = vt16; scale = 1.0f;
        int t = id - 512;
        bn = (t & 31) * BN;
        bm = (t >> 5) * BM;
        N = NTOK;
    }
    hgemm_body<false>(smh, A, W, (void*)C, N, bm, bn, scale);
}

__global__ __launch_bounds__(256, 2) void out_gemm(
    const __half* __restrict__ ctx, const __half* __restrict__ woh,
    float* __restrict__ out)
{
    extern __shared__ __half smh[];
    int bn = (blockIdx.x & 7) * BN;
    int bm = (blockIdx.x >> 3) * BM;
    hgemm_body<true>(smh, ctx, woh, (void*)out, D_MODEL, bm, bn, 1.0f);
}

// ============================================================================
// fp16 tensor-core causal flash attention (m16n8k16) — R13 body (register P),
// with work-ordered grid: (h, b, qt_rev) so the longest causal blocks launch
// first across the whole chip (strictly descending work order).
// smem: Q [128][72] fp16 | K x2 [64][72] | V^T x2 [64][72] = 54 KB -> 2 CTA/SM
// ============================================================================
#define ASTRH 72
#define AQ_OFF    0
#define AK_OFF(b) (128 * ASTRH + (b) * 64 * ASTRH)
#define AV_OFF(b) (128 * ASTRH + 2 * 64 * ASTRH + (b) * 64 * ASTRH)
#define AT_H      (128 * ASTRH + 4 * 64 * ASTRH)
#define AT_BYTES  (AT_H * 2)                 // 55296

__global__ __launch_bounds__(256, 2) void attn_mma(
    const __half* __restrict__ Q, const __half* __restrict__ Kp,
    const __half* __restrict__ Vt, __half* __restrict__ O)
{
    extern __shared__ __half smh[];
    const int tid  = threadIdx.x;
    const int wid  = tid >> 5;
    const int lane = tid & 31;
    const int h    = blockIdx.x;
    const int b    = blockIdx.y;
    const int qt   = (SEQ / 128 - 1) - blockIdx.z;   // longest blocks launch first
    const int q0   = qt * 128;
    const int nkt  = 2 * qt + 2;
    const size_t hb = (size_t)b * SEQ * D_MODEL + (size_t)h * DH;

    auto load_k = [&](int kt, int buf) {
        uint32_t dst = smem_u32(smh + AK_OFF(buf));
        const __half* Kg = Kp + hb + (size_t)kt * 64 * D_MODEL;
#pragma unroll
        for (int i = 0; i < 2; i++) {
            int chunk = tid + 256 * i;       // 0..511
            int row = chunk >> 3, c = chunk & 7;
            CP_ASYNC16(dst + (uint32_t)row * (ASTRH * 2) + c * 16,
                       __cvta_generic_to_global(Kg + (size_t)row * D_MODEL + c * 8));
        }
    };
    auto load_v = [&](int kt, int buf) {
        uint32_t dst = smem_u32(smh + AV_OFF(buf));
        const __half* Vg = Vt + (size_t)h * 64 * NTOK + (size_t)b * SEQ + (size_t)kt * 64;
#pragma unroll
        for (int i = 0; i < 2; i++) {
            int chunk = tid + 256 * i;
            int d = chunk >> 3, c = chunk & 7;
            CP_ASYNC16(dst + (uint32_t)d * (ASTRH * 2) + c * 16,
                       __cvta_generic_to_global(Vg + (size_t)d * NTOK + c * 8));
        }
    };

    // prologue: Q (group0), K0+V0 (group1)
    {
        uint32_t qdst = smem_u32(smh + AQ_OFF);
#pragma unroll
        for (int i = 0; i < 4; i++) {
            int chunk = tid + 256 * i;       // 0..1023
            int row = chunk >> 3, c = chunk & 7;
            CP_ASYNC16(qdst + (uint32_t)row * (ASTRH * 2) + c * 16,
                       __cvta_generic_to_global(Q + hb + (size_t)(q0 + row) * D_MODEL + c * 8));
        }
        CP_COMMIT();
    }
    load_k(0, 0);
    load_v(0, 0);
    CP_COMMIT();

    const int aj   = lane >> 3;
    const int mrow = ((aj & 1) << 3) + (lane & 7);
    const int mcol = (aj >> 1) << 4;
    const int wq   = wid * 16;

    CP_WAIT1();
    __syncthreads();

    // Preload Q fragments (pre-scaled in GEMM epilogue): 4 k16-steps
    uint32_t qfr[4][4];
    {
        uint32_t qa = smem_u32(smh + AQ_OFF) + (uint32_t)(wq + mrow) * (ASTRH * 2) + mcol;
#pragma unroll
        for (int ks = 0; ks < 4; ks++) ldsm_x4(qfr[ks], qa + ks * 32);
    }

    const uint32_t kB[2] = { smem_u32(smh + AK_OFF(0)) + (uint32_t)mrow * (ASTRH * 2) + mcol,
                             smem_u32(smh + AK_OFF(1)) + (uint32_t)mrow * (ASTRH * 2) + mcol };
    const uint32_t vB[2] = { smem_u32(smh + AV_OFF(0)) + (uint32_t)mrow * (ASTRH * 2) + mcol,
                             smem_u32(smh + AV_OFF(1)) + (uint32_t)mrow * (ASTRH * 2) + mcol };

    float oacc[8][4];
#pragma unroll
    for (int nt = 0; nt < 8; nt++)
#pragma unroll
        for (int r = 0; r < 4; r++) oacc[nt][r] = 0.f;
    float m0 = -INFINITY, m1 = -INFINITY, l0 = 0.f, l1 = 0.f;

    const int lr = lane >> 2;
    const int lc = (lane & 3) * 2;

    for (int kt = 0; kt < nkt; kt++) {
        const int buf = kt & 1;
        const int k0  = kt * 64;
        CP_WAIT0();
        __syncthreads();

        if (kt + 1 < nkt) {
            load_k(kt + 1, buf ^ 1);
            load_v(kt + 1, buf ^ 1);
            CP_COMMIT();
        }

        // ---- S = Q K^T : 4 ksteps x 4 p-tiles x 2 mmas = 32 mmas ----
        float sacc[8][4];
#pragma unroll
        for (int nt = 0; nt < 8; nt++)
#pragma unroll
            for (int r = 0; r < 4; r++) sacc[nt][r] = 0.f;

#pragma unroll
        for (int ks = 0; ks < 4; ks++) {
#pragma unroll
            for (int p = 0; p < 4; p++) {
                uint32_t kf[4];
                ldsm_x4(kf, kB[buf] + (uint32_t)(p * 16 * ASTRH * 2) + ks * 32);
                mma_f16(sacc[2 * p],     qfr[ks], kf[0], kf[2]);
                mma_f16(sacc[2 * p + 1], qfr[ks], kf[1], kf[3]);
            }
        }

        const int rg0 = q0 + wq + lr;
        if (kt >= 2 * qt) {
#pragma unroll
            for (int nt = 0; nt < 8; nt++) {
                int cb = k0 + nt * 8 + lc;
                if (cb     > rg0)     sacc[nt][0] = -1e30f;
                if (cb + 1 > rg0)     sacc[nt][1] = -1e30f;
                if (cb     > rg0 + 8) sacc[nt][2] = -1e30f;
                if (cb + 1 > rg0 + 8) sacc[nt][3] = -1e30f;
            }
        }

        // ---- online softmax (log2 domain) ----
        float mx0 = -1e30f, mx1 = -1e30f;
#pragma unroll
        for (int nt = 0; nt < 8; nt++) {
            mx0 = fmaxf(mx0, fmaxf(sacc[nt][0], sacc[nt][1]));
            mx1 = fmaxf(mx1, fmaxf(sacc[nt][2], sacc[nt][3]));
        }
        mx0 = fmaxf(mx0, __shfl_xor_sync(0xffffffffu, mx0, 1));
        mx0 = fmaxf(mx0, __shfl_xor_sync(0xffffffffu, mx0, 2));
        mx1 = fmaxf(mx1, __shfl_xor_sync(0xffffffffu, mx1, 1));
        mx1 = fmaxf(mx1, __shfl_xor_sync(0xffffffffu, mx1, 2));
        float mn0 = fmaxf(m0, mx0), mn1 = fmaxf(m1, mx1);
        float a0 = ex2(m0 - mn0), a1 = ex2(m1 - mn1);
        float rs0 = 0.f, rs1 = 0.f;
#pragma unroll
        for (int nt = 0; nt < 8; nt++) {
            float e0 = ex2(sacc[nt][0] - mn0);
            float e1 = ex2(sacc[nt][1] - mn0);
            float e2 = ex2(sacc[nt][2] - mn1);
            float e3 = ex2(sacc[nt][3] - mn1);
            sacc[nt][0] = e0; sacc[nt][1] = e1; sacc[nt][2] = e2; sacc[nt][3] = e3;
            rs0 += e0 + e1; rs1 += e2 + e3;
        }
        rs0 += __shfl_xor_sync(0xffffffffu, rs0, 1);
        rs0 += __shfl_xor_sync(0xffffffffu, rs0, 2);
        rs1 += __shfl_xor_sync(0xffffffffu, rs1, 1);
        rs1 += __shfl_xor_sync(0xffffffffu, rs1, 2);
        l0 = l0 * a0 + rs0; m0 = mn0;
        l1 = l1 * a1 + rs1; m1 = mn1;
#pragma unroll
        for (int nt = 0; nt < 8; nt++) {
            oacc[nt][0] *= a0; oacc[nt][1] *= a0;
            oacc[nt][2] *= a1; oacc[nt][3] *= a1;
        }

        // ---- O += P V : P fragments built directly from sacc registers ----
#pragma unroll
        for (int ks = 0; ks < 4; ks++) {
            uint32_t pf[4];
            pf[0] = pack_h2(sacc[2 * ks][0],     sacc[2 * ks][1]);
            pf[1] = pack_h2(sacc[2 * ks][2],     sacc[2 * ks][3]);
            pf[2] = pack_h2(sacc[2 * ks + 1][0], sacc[2 * ks + 1][1]);
            pf[3] = pack_h2(sacc[2 * ks + 1][2], sacc[2 * ks + 1][3]);
#pragma unroll
            for (int p = 0; p < 4; p++) {
                uint32_t vf[4];
                ldsm_x4(vf, vB[buf] + (uint32_t)(p * 16 * ASTRH * 2) + ks * 32);
                mma_f16(oacc[2 * p],     pf, vf[0], vf[2]);
                mma_f16(oacc[2 * p + 1], pf, vf[1], vf[3]);
            }
        }
    }

    // ---- epilogue: fp16 ctx ----
    const float i0 = 1.f / l0, i1 = 1.f / l1;
    const int row0 = q0 + wq + lr;
    __half* Ob = O + (size_t)(b * SEQ + row0) * D_MODEL + (size_t)h * DH + lc;
#pragma unroll
    for (int nt = 0; nt < 8; nt++) {
        *reinterpret_cast<__half2*>(Ob + nt * 8)
            = __floats2half2_rn(oacc[nt][0] * i0, oacc[nt][1] * i0);
        *reinterpret_cast<__half2*>(Ob + 8 * D_MODEL + nt * 8)
            = __floats2half2_rn(oacc[nt][2] * i1, oacc[nt][3] * i1);
    }
}

// ---------------------------------------------------------------------------
extern "C" void kernel_launch(void* const* d_in, const int* in_sizes, int n_in,
                              void* d_out, int out_size)
{
    const float* x  = (const float*)d_in[0];
    const float* Wq = (const float*)d_in[1];
    const float* Wk = (const float*)d_in[2];
    const float* Wv = (const float*)d_in[3];
    const float* Wo = (const float*)d_in[4];
    float* out = (float*)d_out;

    __half *xh, *wqh, *wkh, *wvh, *woh, *q16, *k16, *vt16, *ctx;
    cudaGetSymbolAddress((void**)&xh,   g_xh);
    cudaGetSymbolAddress((void**)&wqh,  g_wqh);
    cudaGetSymbolAddress((void**)&wkh,  g_wkh);
    cudaGetSymbolAddress((void**)&wvh,  g_wvh);
    cudaGetSymbolAddress((void**)&woh,  g_woh);
    cudaGetSymbolAddress((void**)&q16,  g_q16);
    cudaGetSymbolAddress((void**)&k16,  g_k16);
    cudaGetSymbolAddress((void**)&vt16, g_vt16);
    cudaGetSymbolAddress((void**)&ctx,  g_ctx);

    cudaFuncSetAttribute(qkv_gemm, cudaFuncAttributeMaxDynamicSharedMemorySize, GSMEM_BYTES);
    cudaFuncSetAttribute(out_gemm, cudaFuncAttributeMaxDynamicSharedMemorySize, GSMEM_BYTES);
    cudaFuncSetAttribute(attn_mma, cudaFuncAttributeMaxDynamicSharedMemorySize, AT_BYTES);

    // All fp32 -> fp16 conversions in ONE launch (8192 blocks)
    f2h_all<<<8192, 256>>>(x, Wq, Wk, Wv, Wo, xh, wqh, wkh, wvh, woh);

    // All three projection GEMMs in ONE wave-merged launch (768 CTAs)
    qkv_gemm<<<768, 256, GSMEM_BYTES>>>(xh, wqh, wkh, wvh, q16, k16, vt16);

    // Attention: grid (h, b, qt_rev) — longest causal blocks first
    attn_mma<<<dim3(NH, BATCH, SEQ / 128), 256, AT_BYTES>>>(q16, k16, vt16, ctx);

    out_gemm<<<256, 256, GSMEM_BYTES>>>(ctx, woh, out);
}

// round 17
// speedup vs baseline: 1.2303x; 1.0392x over previous
#include <cuda_runtime.h>
#include <cuda_fp16.h>
#include <math.h>
#include <stdint.h>

#define D_MODEL 1024
#define NH      16
#define DH      64
#define BATCH   2
#define SEQ     2048
#define NTOK    (BATCH * SEQ)   // 4096

// Scratch (device globals — no runtime allocation allowed)
__device__ __half g_xh [NTOK * D_MODEL];
__device__ __half g_wqh[D_MODEL * D_MODEL];
__device__ __half g_wkh[D_MODEL * D_MODEL];
__device__ __half g_wvh[D_MODEL * D_MODEL];
__device__ __half g_woh[D_MODEL * D_MODEL];
__device__ __half g_q16 [NTOK * D_MODEL];      // Q fp16, pre-scaled by 0.125*log2(e)
__device__ __half g_k16 [NTOK * D_MODEL];      // K fp16 [token][chan]
__device__ __half g_vt16[D_MODEL * NTOK];      // V^T fp16 [chan][token]
__device__ __half g_ctx [NTOK * D_MODEL];      // attention output fp16

__device__ __forceinline__ uint32_t smem_u32(const void* p) {
    uint32_t a;
    asm("{ .reg .u64 t; cvta.to.shared.u64 t, %1; cvt.u32.u64 %0, t; }" : "=r"(a) : "l"(p));
    return a;
}
__device__ __forceinline__ void ldsm_x4(uint32_t (&r)[4], uint32_t addr) {
    asm volatile("ldmatrix.sync.aligned.m8n8.x4.shared.b16 {%0,%1,%2,%3}, [%4];"
                 : "=r"(r[0]), "=r"(r[1]), "=r"(r[2]), "=r"(r[3]) : "r"(addr));
}
__device__ __forceinline__ void mma_f16(float (&c)[4], const uint32_t a[4],
                                        uint32_t b0, uint32_t b1) {
    asm volatile(
        "mma.sync.aligned.m16n8k16.row.col.f32.f16.f16.f32 "
        "{%0,%1,%2,%3}, {%4,%5,%6,%7}, {%8,%9}, {%0,%1,%2,%3};"
        : "+f"(c[0]), "+f"(c[1]), "+f"(c[2]), "+f"(c[3])
        : "r"(a[0]), "r"(a[1]), "r"(a[2]), "r"(a[3]), "r"(b0), "r"(b1));
}
__device__ __forceinline__ float ex2(float x) {
    float y; asm("ex2.approx.f32 %0, %1;" : "=f"(y) : "f"(x)); return y;
}
__device__ __forceinline__ uint32_t pack_h2(float a, float b) {
    __half2 h = __floats2half2_rn(a, b);
    return *reinterpret_cast<uint32_t*>(&h);
}
// packed fp16x2 exp2 — one MUFU op for two exponentials
__device__ __forceinline__ uint32_t ex2_h2(uint32_t x) {
    uint32_t y;
    asm("ex2.approx.f16x2 %0, %1;" : "=r"(y) : "r"(x));
    return y;
}
#define CP_ASYNC16(dst, src) \
    asm volatile("cp.async.cg.shared.global [%0], [%1], 16;" :: "r"(dst), "l"(src) : "memory")
#define CP_COMMIT() asm volatile("cp.async.commit_group;" ::: "memory")
#define CP_WAIT0()  asm volatile("cp.async.wait_group 0;" ::: "memory")
#define CP_WAIT1()  asm volatile("cp.async.wait_group 1;" ::: "memory")

// ============================================================================
// Merged fp32 -> fp16 conversion (one launch, 8192 blocks).
// ============================================================================
__global__ __launch_bounds__(256) void f2h_all(
    const float* __restrict__ x,
    const float* __restrict__ wq, const float* __restrict__ wk,
    const float* __restrict__ wv, const float* __restrict__ wo,
    __half* __restrict__ xh,
    __half* __restrict__ wqh, __half* __restrict__ wkh,
    __half* __restrict__ wvh, __half* __restrict__ woh)
{
    const int id = blockIdx.x;
    const float* in;
    __half* out;
    int boff;
    if (id < 4096) { in = x; out = xh; boff = id; }
    else {
        int w = (id - 4096) >> 10;
        boff  = (id - 4096) & 1023;
        in  = (w == 0) ? wq : (w == 1) ? wk : (w == 2) ? wv : wo;
        out = (w == 0) ? wqh : (w == 1) ? wkh : (w == 2) ? wvh : woh;
    }
    int i = (boff * 256 + threadIdx.x) * 4;
    float4 v = *reinterpret_cast<const float4*>(in + i);
    __half2 h0 = __floats2half2_rn(v.x, v.y);
    __half2 h1 = __floats2half2_rn(v.z, v.w);
    uint2 pk = make_uint2(*reinterpret_cast<uint32_t*>(&h0),
                          *reinterpret_cast<uint32_t*>(&h1));
    *reinterpret_cast<uint2*>(out + i) = pk;
}

// ============================================================================
// Shared fp16 GEMM body — ONE __syncthreads per ktile.
// ============================================================================
#define BM 128
#define BN 128
#define BKH 64
#define KSTRH 72
#define TILE_H (BM * KSTRH)
#define GSMEM_BYTES (4 * TILE_H * 2)
#define GK 1024

#define QSCALEF (0.125f * 1.4426950408889634f)

template <bool FP32OUT>
__device__ __forceinline__ void hgemm_body(
    __half* smh, const __half* __restrict__ A, const __half* __restrict__ W,
    void* __restrict__ Cv, int N, int bm, int bn, float scale)
{
    __half* AsP[2] = { smh,              smh + TILE_H };
    __half* BsP[2] = { smh + 2 * TILE_H, smh + 3 * TILE_H };

    const int tid  = threadIdx.x;
    const int wid  = tid >> 5;
    const int lane = tid & 31;
    const int wm = (wid >> 2) * 64;
    const int wn = (wid & 3) * 32;

    float acc[4][4][4];
#pragma unroll
    for (int i = 0; i < 4; i++)
#pragma unroll
        for (int j = 0; j < 4; j++)
#pragma unroll
            for (int q = 0; q < 4; q++) acc[i][j][q] = 0.f;

    const int aj   = lane >> 3;
    const int mrow = ((aj & 1) << 3) + (lane & 7);
    const int mcol = (aj >> 1) << 4;

    uint32_t aBase[2], bBase[2];
#pragma unroll
    for (int buf = 0; buf < 2; buf++) {
        aBase[buf] = smem_u32(AsP[buf]) + (uint32_t)(wm + mrow) * (KSTRH * 2) + mcol;
        bBase[buf] = smem_u32(BsP[buf]) + (uint32_t)(wn + mrow) * (KSTRH * 2) + mcol;
    }

    const __half* Ap = A + (size_t)bm * GK;
    const __half* Wp = W + (size_t)bn * GK;
    const int KT = GK / BKH;

    auto load_tile = [&](int t, int buf) {
        const __half* Ag = Ap + t * BKH;
        const __half* Bg = Wp + t * BKH;
        uint32_t sa = smem_u32(AsP[buf]);
        uint32_t sb = smem_u32(BsP[buf]);
#pragma unroll
        for (int i = 0; i < 4; i++) {
            int chunk = tid + 256 * i;
            int row = chunk >> 3;
            int c   = chunk & 7;
            uint32_t so = (uint32_t)row * (KSTRH * 2) + c * 16;
            CP_ASYNC16(sa + so, __cvta_generic_to_global(Ag + (size_t)row * GK + c * 8));
            CP_ASYNC16(sb + so, __cvta_generic_to_global(Bg + (size_t)row * GK + c * 8));
        }
        CP_COMMIT();
    };

    load_tile(0, 0);

    for (int t = 0; t < KT; t++) {
        const int buf = t & 1;
        CP_WAIT0();
        __syncthreads();
        if (t + 1 < KT) load_tile(t + 1, buf ^ 1);

#pragma unroll
        for (int ks = 0; ks < 4; ks++) {
            uint32_t afr[4][4], bfr[2][4];
#pragma unroll
            for (int mt = 0; mt < 4; mt++)
                ldsm_x4(afr[mt], aBase[buf] + (uint32_t)(mt * 16 * KSTRH * 2) + ks * 32);
#pragma unroll
            for (int p = 0; p < 2; p++)
                ldsm_x4(bfr[p], bBase[buf] + (uint32_t)(p * 16 * KSTRH * 2) + ks * 32);
#pragma unroll
            for (int mt = 0; mt < 4; mt++) {
#pragma unroll
                for (int p = 0; p < 2; p++) {
                    mma_f16(acc[mt][2 * p],     afr[mt], bfr[p][0], bfr[p][2]);
                    mma_f16(acc[mt][2 * p + 1], afr[mt], bfr[p][1], bfr[p][3]);
                }
            }
        }
    }

    const int rr = lane >> 2;
    const int cc = (lane & 3) * 2;
#pragma unroll
    for (int mt = 0; mt < 4; mt++) {
#pragma unroll
        for (int nt = 0; nt < 4; nt++) {
            int row = bm + wm + mt * 16 + rr;
            int col = bn + wn + nt * 8 + cc;
            if (FP32OUT) {
                float* Cp = (float*)Cv;
                *reinterpret_cast<float2*>(Cp + (size_t)row * N + col)
                    = make_float2(acc[mt][nt][0], acc[mt][nt][1]);
                *reinterpret_cast<float2*>(Cp + (size_t)(row + 8) * N + col)
                    = make_float2(acc[mt][nt][2], acc[mt][nt][3]);
            } else {
                __half* Cp = (__half*)Cv;
                __half2 v0 = __floats2half2_rn(acc[mt][nt][0] * scale, acc[mt][nt][1] * scale);
                __half2 v1 = __floats2half2_rn(acc[mt][nt][2] * scale, acc[mt][nt][3] * scale);
                *reinterpret_cast<__half2*>(Cp + (size_t)row * N + col)       = v0;
                *reinterpret_cast<__half2*>(Cp + (size_t)(row + 8) * N + col) = v1;
            }
        }
    }
}

// Merged Q/K/V^T GEMM: 768 CTAs in ONE launch
__global__ __launch_bounds__(256, 2) void qkv_gemm(
    const __half* __restrict__ xh,
    const __half* __restrict__ wqh, const __half* __restrict__ wkh,
    const __half* __restrict__ wvh,
    __half* __restrict__ q16, __half* __restrict__ k16, __half* __restrict__ vt16)
{
    extern __shared__ __half smh[];
    const int id = blockIdx.x;
    const __half *A, *W;
    __half* C;
    int N, bm, bn;
    float scale;
    if (id < 512) {
        A = xh;
        W = (id < 256) ? wqh : wkh;
        C = (id < 256) ? q16 : k16;
        scale = (id < 256) ? QSCALEF : 1.0f;
        int t = id & 255;
        bn = (t & 7) * BN;
        bm = (t >> 3) * BM;
        N = D_MODEL;
    } else {
        A = wvh; W = xh; C = vt16; scale = 1.0f;
        int t = id - 512;
        bn = (t & 31) * BN;
        bm = (t >> 5) * BM;
        N = NTOK;
    }
    hgemm_body<false>(smh, A, W, (void*)C, N, bm, bn, scale);
}

__global__ __launch_bounds__(256, 2) void out_gemm(
    const __half* __restrict__ ctx, const __half* __restrict__ woh,
    float* __restrict__ out)
{
    extern __shared__ __half smh[];
    int bn = (blockIdx.x & 7) * BN;
    int bm = (blockIdx.x >> 3) * BM;
    hgemm_body<true>(smh, ctx, woh, (void*)out, D_MODEL, bm, bn, 1.0f);
}

// ============================================================================
// fp16 causal flash attention — R17:
//  * exp via ex2.approx.f16x2 into packed P fragments (MUFU /2)
//  * row-sum l via ALL-ONES-B mma (every column = row sum -> every lane valid)
//  * work-ordered grid (h, b, qt_rev)
// smem: Q [128][72] | K x2 [64][72] | V^T x2 [64][72] = 54 KB -> 2 CTA/SM
// ============================================================================
#define ASTRH 72
#define AQ_OFF    0
#define AK_OFF(b) (128 * ASTRH + (b) * 64 * ASTRH)
#define AV_OFF(b) (128 * ASTRH + 2 * 64 * ASTRH + (b) * 64 * ASTRH)
#define AT_H      (128 * ASTRH + 4 * 64 * ASTRH)
#define AT_BYTES  (AT_H * 2)                 // 55296

__global__ __launch_bounds__(256, 2) void attn_mma(
    const __half* __restrict__ Q, const __half* __restrict__ Kp,
    const __half* __restrict__ Vt, __half* __restrict__ O)
{
    extern __shared__ __half smh[];
    const int tid  = threadIdx.x;
    const int wid  = tid >> 5;
    const int lane = tid & 31;
    const int h    = blockIdx.x;
    const int b    = blockIdx.y;
    const int qt   = (SEQ / 128 - 1) - blockIdx.z;   // longest blocks first
    const int q0   = qt * 128;
    const int nkt  = 2 * qt + 2;
    const size_t hb = (size_t)b * SEQ * D_MODEL + (size_t)h * DH;

    auto load_k = [&](int kt, int buf) {
        uint32_t dst = smem_u32(smh + AK_OFF(buf));
        const __half* Kg = Kp + hb + (size_t)kt * 64 * D_MODEL;
#pragma unroll
        for (int i = 0; i < 2; i++) {
            int chunk = tid + 256 * i;
            int row = chunk >> 3, c = chunk & 7;
            CP_ASYNC16(dst + (uint32_t)row * (ASTRH * 2) + c * 16,
                       __cvta_generic_to_global(Kg + (size_t)row * D_MODEL + c * 8));
        }
    };
    auto load_v = [&](int kt, int buf) {
        uint32_t dst = smem_u32(smh + AV_OFF(buf));
        const __half* Vg = Vt + (size_t)h * 64 * NTOK + (size_t)b * SEQ + (size_t)kt * 64;
#pragma unroll
        for (int i = 0; i < 2; i++) {
            int chunk = tid + 256 * i;
            int d = chunk >> 3, c = chunk & 7;
            CP_ASYNC16(dst + (uint32_t)d * (ASTRH * 2) + c * 16,
                       __cvta_generic_to_global(Vg + (size_t)d * NTOK + c * 8));
        }
    };

    // prologue: Q (group0), K0+V0 (group1)
    {
        uint32_t qdst = smem_u32(smh + AQ_OFF);
#pragma unroll
        for (int i = 0; i < 4; i++) {
            int chunk = tid + 256 * i;
            int row = chunk >> 3, c = chunk & 7;
            CP_ASYNC16(qdst + (uint32_t)row * (ASTRH * 2) + c * 16,
                       __cvta_generic_to_global(Q + hb + (size_t)(q0 + row) * D_MODEL + c * 8));
        }
        CP_COMMIT();
    }
    load_k(0, 0);
    load_v(0, 0);
    CP_COMMIT();

    const int aj   = lane >> 3;
    const int mrow = ((aj & 1) << 3) + (lane & 7);
    const int mcol = (aj >> 1) << 4;
    const int wq   = wid * 16;

    CP_WAIT1();
    __syncthreads();

    // Preload Q fragments
    uint32_t qfr[4][4];
    {
        uint32_t qa = smem_u32(smh + AQ_OFF) + (uint32_t)(wq + mrow) * (ASTRH * 2) + mcol;
#pragma unroll
        for (int ks = 0; ks < 4; ks++) ldsm_x4(qfr[ks], qa + ks * 32);
    }

    const uint32_t kB[2] = { smem_u32(smh + AK_OFF(0)) + (uint32_t)mrow * (ASTRH * 2) + mcol,
                             smem_u32(smh + AK_OFF(1)) + (uint32_t)mrow * (ASTRH * 2) + mcol };
    const uint32_t vB[2] = { smem_u32(smh + AV_OFF(0)) + (uint32_t)mrow * (ASTRH * 2) + mcol,
                             smem_u32(smh + AV_OFF(1)) + (uint32_t)mrow * (ASTRH * 2) + mcol };

    // B fragment = ALL ones (16x8 ones): every output column = row sum, so
    // every lane's lacc holds the correct l regardless of which column it owns.
    const uint32_t one_b = 0x3C003C00u;

    float oacc[8][4];
#pragma unroll
    for (int nt = 0; nt < 8; nt++)
#pragma unroll
        for (int r = 0; r < 4; r++) oacc[nt][r] = 0.f;
    float lacc[4] = {0.f, 0.f, 0.f, 0.f};   // lacc[0]=l(row lr), lacc[2]=l(row lr+8)
    float m0 = -INFINITY, m1 = -INFINITY;

    const int lr = lane >> 2;
    const int lc = (lane & 3) * 2;

    for (int kt = 0; kt < nkt; kt++) {
        const int buf = kt & 1;
        const int k0  = kt * 64;
        CP_WAIT0();
        __syncthreads();

        if (kt + 1 < nkt) {
            load_k(kt + 1, buf ^ 1);
            load_v(kt + 1, buf ^ 1);
            CP_COMMIT();
        }

        // ---- S = Q K^T ----
        float sacc[8][4];
#pragma unroll
        for (int nt = 0; nt < 8; nt++)
#pragma unroll
            for (int r = 0; r < 4; r++) sacc[nt][r] = 0.f;

#pragma unroll
        for (int ks = 0; ks < 4; ks++) {
#pragma unroll
            for (int p = 0; p < 4; p++) {
                uint32_t kf[4];
                ldsm_x4(kf, kB[buf] + (uint32_t)(p * 16 * ASTRH * 2) + ks * 32);
                mma_f16(sacc[2 * p],     qfr[ks], kf[0], kf[2]);
                mma_f16(sacc[2 * p + 1], qfr[ks], kf[1], kf[3]);
            }
        }

        const int rg0 = q0 + wq + lr;
        if (kt >= 2 * qt) {
#pragma unroll
            for (int nt = 0; nt < 8; nt++) {
                int cb = k0 + nt * 8 + lc;
                if (cb     > rg0)     sacc[nt][0] = -1e30f;
                if (cb + 1 > rg0)     sacc[nt][1] = -1e30f;
                if (cb     > rg0 + 8) sacc[nt][2] = -1e30f;
                if (cb + 1 > rg0 + 8) sacc[nt][3] = -1e30f;
            }
        }

        // ---- online softmax: max reduce only (sum comes from ones-mma) ----
        float mx0 = -1e30f, mx1 = -1e30f;
#pragma unroll
        for (int nt = 0; nt < 8; nt++) {
            mx0 = fmaxf(mx0, fmaxf(sacc[nt][0], sacc[nt][1]));
            mx1 = fmaxf(mx1, fmaxf(sacc[nt][2], sacc[nt][3]));
        }
        mx0 = fmaxf(mx0, __shfl_xor_sync(0xffffffffu, mx0, 1));
        mx0 = fmaxf(mx0, __shfl_xor_sync(0xffffffffu, mx0, 2));
        mx1 = fmaxf(mx1, __shfl_xor_sync(0xffffffffu, mx1, 1));
        mx1 = fmaxf(mx1, __shfl_xor_sync(0xffffffffu, mx1, 2));
        float mn0 = fmaxf(m0, mx0), mn1 = fmaxf(m1, mx1);
        float a0 = ex2(m0 - mn0), a1 = ex2(m1 - mn1);
        m0 = mn0; m1 = mn1;
        lacc[0] *= a0; lacc[1] *= a0; lacc[2] *= a1; lacc[3] *= a1;
#pragma unroll
        for (int nt = 0; nt < 8; nt++) {
            oacc[nt][0] *= a0; oacc[nt][1] *= a0;
            oacc[nt][2] *= a1; oacc[nt][3] *= a1;
        }

        // ---- O += P V, l += P·1 : P built via packed fp16x2 exp2 ----
#pragma unroll
        for (int ks = 0; ks < 4; ks++) {
            uint32_t pf[4];
            pf[0] = ex2_h2(pack_h2(sacc[2 * ks][0] - mn0,     sacc[2 * ks][1] - mn0));
            pf[1] = ex2_h2(pack_h2(sacc[2 * ks][2] - mn1,     sacc[2 * ks][3] - mn1));
            pf[2] = ex2_h2(pack_h2(sacc[2 * ks + 1][0] - mn0, sacc[2 * ks + 1][1] - mn0));
            pf[3] = ex2_h2(pack_h2(sacc[2 * ks + 1][2] - mn1, sacc[2 * ks + 1][3] - mn1));
            mma_f16(lacc, pf, one_b, one_b);          // all columns = row sum
#pragma unroll
            for (int p = 0; p < 4; p++) {
                uint32_t vf[4];
                ldsm_x4(vf, vB[buf] + (uint32_t)(p * 16 * ASTRH * 2) + ks * 32);
                mma_f16(oacc[2 * p],     pf, vf[0], vf[2]);
                mma_f16(oacc[2 * p + 1], pf, vf[1], vf[3]);
            }
        }
    }

    // ---- epilogue: fp16 ctx ----
    const float i0 = 1.f / lacc[0], i1 = 1.f / lacc[2];
    const int row0 = q0 + wq + lr;
    __half* Ob = O + (size_t)(b * SEQ + row0) * D_MODEL + (size_t)h * DH + lc;
#pragma unroll
    for (int nt = 0; nt < 8; nt++) {
        *reinterpret_cast<__half2*>(Ob + nt * 8)
            = __floats2half2_rn(oacc[nt][0] * i0, oacc[nt][1] * i0);
        *reinterpret_cast<__half2*>(Ob + 8 * D_MODEL + nt * 8)
            = __floats2half2_rn(oacc[nt][2] * i1, oacc[nt][3] * i1);
    }
}

// ---------------------------------------------------------------------------
extern "C" void kernel_launch(void* const* d_in, const int* in_sizes, int n_in,
                              void* d_out, int out_size)
{
    const float* x  = (const float*)d_in[0];
    const float* Wq = (const float*)d_in[1];
    const float* Wk = (const float*)d_in[2];
    const float* Wv = (const float*)d_in[3];
    const float* Wo = (const float*)d_in[4];
    float* out = (float*)d_out;

    __half *xh, *wqh, *wkh, *wvh, *woh, *q16, *k16, *vt16, *ctx;
    cudaGetSymbolAddress((void**)&xh,   g_xh);
    cudaGetSymbolAddress((void**)&wqh,  g_wqh);
    cudaGetSymbolAddress((void**)&wkh,  g_wkh);
    cudaGetSymbolAddress((void**)&wvh,  g_wvh);
    cudaGetSymbolAddress((void**)&woh,  g_woh);
    cudaGetSymbolAddress((void**)&q16,  g_q16);
    cudaGetSymbolAddress((void**)&k16,  g_k16);
    cudaGetSymbolAddress((void**)&vt16, g_vt16);
    cudaGetSymbolAddress((void**)&ctx,  g_ctx);

    cudaFuncSetAttribute(qkv_gemm, cudaFuncAttributeMaxDynamicSharedMemorySize, GSMEM_BYTES);
    cudaFuncSetAttribute(out_gemm, cudaFuncAttributeMaxDynamicSharedMemorySize, GSMEM_BYTES);
    cudaFuncSetAttribute(attn_mma, cudaFuncAttributeMaxDynamicSharedMemorySize, AT_BYTES);

    f2h_all<<<8192, 256>>>(x, Wq, Wk, Wv, Wo, xh, wqh, wkh, wvh, woh);

    qkv_gemm<<<768, 256, GSMEM_BYTES>>>(xh, wqh, wkh, wvh, q16, k16, vt16);

    attn_mma<<<dim3(NH, BATCH, SEQ / 128), 256, AT_BYTES>>>(q16, k16, vt16, ctx);

    out_gemm<<<256, 256, GSMEM_BYTES>>>(ctx, woh, out);
}